// round 1
// baseline (speedup 1.0000x reference)
#include <cuda_runtime.h>

#define Dg   128
#define TMt  32
#define TVt  32
#define EPSF 1e-8f
#define NMAX 16384
#define VMAX 8192

__device__ float g_x2[NMAX];
__device__ float g_c2[VMAX];

typedef unsigned long long u64;

__device__ __forceinline__ void fma2(u64 &d, u64 a, u64 b) {
    asm("fma.rn.f32x2 %0, %1, %2, %0;" : "+l"(d) : "l"(a), "l"(b));
}
__device__ __forceinline__ float2 unpack2(u64 v) {
    float2 r; asm("mov.b64 {%0, %1}, %2;" : "=f"(r.x), "=f"(r.y) : "l"(v)); return r;
}
__device__ __forceinline__ u64 pack2(float lo, float hi) {
    u64 r; asm("mov.b64 %0, {%1, %2};" : "=l"(r) : "f"(lo), "f"(hi)); return r;
}

// Pre-kernel: row norms of x and codebook. One warp per row.
__global__ void norms_kernel(const float* __restrict__ x,
                             const float* __restrict__ cb, int n, int v) {
    int gw   = (blockIdx.x * blockDim.x + threadIdx.x) >> 5;
    int lane = threadIdx.x & 31;
    int total = n + v;
    if (gw >= total) return;
    const float* src = (gw < n) ? (x + (size_t)gw * Dg)
                                : (cb + (size_t)(gw - n) * Dg);
    float4 val = ((const float4*)src)[lane];
    float s = val.x*val.x + val.y*val.y + val.z*val.z + val.w*val.w;
    #pragma unroll
    for (int off = 16; off; off >>= 1) s += __shfl_xor_sync(0xffffffffu, s, off);
    if (lane == 0) { if (gw < n) g_x2[gw] = s; else g_c2[gw - n] = s; }
}

// Fused SoftVQ: per block, 32 x-rows; stream codebook in 32-row tiles.
// Phase S: distance tile (f32x2 FMA).  Phase B: O += W_tile @ C_tile (f32x2 FMA).
__global__ __launch_bounds__(256) void softvq_kernel(
    const float* __restrict__ x, const float* __restrict__ cb,
    float* __restrict__ out_embed, float* __restrict__ out_idx,
    int n, int v)
{
    __shared__ float xs[TMt][Dg];          // 16 KB
    __shared__ float cs[TVt][Dg + 4];      // stride 132: LDS.128 lane-varying conflict-free
    __shared__ float wsm[TMt][TVt + 1];    // stride 33: conflict-free row-varying reads
    __shared__ float rowsum[TMt];
    __shared__ int   rowidx[TMt];

    const int t    = threadIdx.x;
    const int lane = t & 31;
    const int warp = t >> 5;
    const int m0   = blockIdx.x * TMt;

    // Load x tile (coalesced float4): thread -> (row = t/8, 16-float segment = t%8)
    {
        int r = t >> 3, s = t & 7;
        const float4* src = (const float4*)(x + (size_t)(m0 + r) * Dg + s * 16);
        float4* dst = (float4*)&xs[r][s * 16];
        #pragma unroll
        for (int i = 0; i < 4; i++) dst[i] = src[i];
    }

    float x2r[4];
    #pragma unroll
    for (int j = 0; j < 4; j++) x2r[j] = g_x2[m0 + 4 * warp + j];

    // Output accumulators: thread owns (row = lane, cols warp*16 .. +16) as 8 f32x2
    u64 o2[8];
    #pragma unroll
    for (int i = 0; i < 8; i++) o2[i] = 0ull;
    // Per-row running scalars: warp w owns rows 4w..4w+3, lane owns v ≡ lane (mod 32)
    float psum[4]  = {0.f, 0.f, 0.f, 0.f};
    float pmind[4]; int pmini[4];
    #pragma unroll
    for (int j = 0; j < 4; j++) { pmind[j] = 3.4e38f; pmini[j] = 0; }

    for (int vt = 0; vt < v; vt += TVt) {
        __syncthreads();  // cs/wsm safe to overwrite (covers prior B phase; and xs load on iter 0)
        {   // load codebook tile (coalesced)
            int r = t >> 3, s = t & 7;
            const float4* src = (const float4*)(cb + (size_t)(vt + r) * Dg + s * 16);
            #pragma unroll
            for (int i = 0; i < 4; i++) *((float4*)&cs[r][s * 16 + 4 * i]) = src[i];
        }
        __syncthreads();

        const float c2v = g_c2[vt + lane];

        // ---- Phase S: S[4w+j][lane] = <x_row, c_lane> ----
        u64 acc2[4] = {0ull, 0ull, 0ull, 0ull};
        #pragma unroll 8
        for (int k = 0; k < Dg; k += 4) {
            ulonglong2 cq = *(const ulonglong2*)&cs[lane][k];      // lane-varying, conflict-free
            #pragma unroll
            for (int j = 0; j < 4; j++) {
                ulonglong2 xq = *(const ulonglong2*)&xs[4 * warp + j][k];  // broadcast
                fma2(acc2[j], xq.x, cq.x);
                fma2(acc2[j], xq.y, cq.y);
            }
        }
        #pragma unroll
        for (int j = 0; j < 4; j++) {
            float2 p = unpack2(acc2[j]);
            float s  = p.x + p.y;
            float d2 = x2r[j] + c2v - 2.0f * s;
            float dd = sqrtf(fmaxf(d2, 0.0f));
            float wv = dd + EPSF;
            wsm[4 * warp + j][lane] = wv;
            psum[j] += wv;
            if (dd < pmind[j]) { pmind[j] = dd; pmini[j] = vt + lane; }
        }
        __syncthreads();

        // ---- Phase B: O[lane][warp*16+..] += sum_v wsm[lane][v] * cs[v][..] ----
        #pragma unroll 4
        for (int vv = 0; vv < TVt; vv++) {
            float wv = wsm[lane][vv];            // stride 33 -> conflict-free
            u64 wv2 = pack2(wv, wv);
            const ulonglong2* cp = (const ulonglong2*)&cs[vv][warp * 16];  // broadcast
            #pragma unroll
            for (int i = 0; i < 4; i++) {
                ulonglong2 cq = cp[i];
                fma2(o2[2 * i],     cq.x, wv2);
                fma2(o2[2 * i + 1], cq.y, wv2);
            }
        }
    }

    // Cross-lane reduce: sum, and min with first-occurrence tie-break
    #pragma unroll
    for (int off = 16; off; off >>= 1) {
        #pragma unroll
        for (int j = 0; j < 4; j++) {
            psum[j] += __shfl_xor_sync(0xffffffffu, psum[j], off);
            float od = __shfl_xor_sync(0xffffffffu, pmind[j], off);
            int   oi = __shfl_xor_sync(0xffffffffu, pmini[j], off);
            if (od < pmind[j] || (od == pmind[j] && oi < pmini[j])) {
                pmind[j] = od; pmini[j] = oi;
            }
        }
    }
    if (lane == 0) {
        #pragma unroll
        for (int j = 0; j < 4; j++) {
            rowsum[4 * warp + j] = psum[j];
            rowidx[4 * warp + j] = pmini[j];
        }
    }
    __syncthreads();

    {   // embed out: normalize by row sum
        float inv = 1.0f / rowsum[lane];
        float* op = out_embed + (size_t)(m0 + lane) * Dg + warp * 16;
        #pragma unroll
        for (int i = 0; i < 4; i++) {
            float2 a = unpack2(o2[2 * i]);
            float2 b = unpack2(o2[2 * i + 1]);
            ((float4*)op)[i] = make_float4(a.x * inv, a.y * inv, b.x * inv, b.y * inv);
        }
    }
    if (out_idx != nullptr && t < TMt) out_idx[m0 + t] = (float)rowidx[t];
}

extern "C" void kernel_launch(void* const* d_in, const int* in_sizes, int n_in,
                              void* d_out, int out_size) {
    const float* x  = (const float*)d_in[0];
    const float* cb = (const float*)d_in[1];
    int n = in_sizes[0] / Dg;   // 16384
    int v = in_sizes[1] / Dg;   // 8192
    float* out  = (float*)d_out;
    // Output convention: embed [n*128] then idxes [n] (cast to output dtype).
    float* oidx = ((long long)out_size >= (long long)n * Dg + n)
                      ? out + (size_t)n * Dg : nullptr;

    int warps_needed = n + v;
    int nblocks = (warps_needed * 32 + 255) / 256;
    norms_kernel<<<nblocks, 256>>>(x, cb, n, v);
    softvq_kernel<<<n / TMt, 256>>>(x, cb, out, oidx, n, v);
}

// round 4
// speedup vs baseline: 2.7848x; 2.7848x over previous
#include <cuda_runtime.h>
#include <cstdint>

#define D128 128
#define VT   64
#define MCTA 128
#define EPSF 1e-8f

__device__ float g_x2[16384];
__device__ float g_c2[8192];

// smem float offsets (row stride 132 => all mma fragment loads conflict-free)
#define XH  0
#define XL  16896
#define CHo 33792
#define CLo 42240
#define C2S 50688
#define SMEM_FLOATS 50752   // 203,008 bytes

static __device__ __forceinline__ uint32_t tf32_rna(float x) {
    uint32_t r; asm("cvt.rna.tf32.f32 %0, %1;" : "=r"(r) : "f"(x)); return r;
}
static __device__ __forceinline__ uint32_t fbits(float x) { return __float_as_uint(x); }

static __device__ __forceinline__ void mma8(float* d, const uint32_t* a,
                                            uint32_t b0, uint32_t b1) {
    asm volatile("mma.sync.aligned.m16n8k8.row.col.f32.tf32.tf32.f32 "
        "{%0,%1,%2,%3}, {%4,%5,%6,%7}, {%8,%9}, {%0,%1,%2,%3};"
        : "+f"(d[0]), "+f"(d[1]), "+f"(d[2]), "+f"(d[3])
        : "r"(a[0]), "r"(a[1]), "r"(a[2]), "r"(a[3]), "r"(b0), "r"(b1));
}

// -------- norms pre-kernel (one warp per row) --------
__global__ void norms_kernel(const float* __restrict__ x,
                             const float* __restrict__ cb, int n, int v) {
    int gw   = (blockIdx.x * blockDim.x + threadIdx.x) >> 5;
    int lane = threadIdx.x & 31;
    if (gw >= n + v) return;
    const float* src = (gw < n) ? (x + (size_t)gw * D128) : (cb + (size_t)(gw - n) * D128);
    float4 val = ((const float4*)src)[lane];
    float s = val.x*val.x + val.y*val.y + val.z*val.z + val.w*val.w;
    #pragma unroll
    for (int off = 16; off; off >>= 1) s += __shfl_xor_sync(0xffffffffu, s, off);
    if (lane == 0) { if (gw < n) g_x2[gw] = s; else g_c2[gw - n] = s; }
}

// -------- fused SoftVQ via mma.sync tf32 (split precision) --------
__global__ void __launch_bounds__(256, 1) softvq_mma(
    const float* __restrict__ x, const float* __restrict__ cb,
    float* __restrict__ out_embed, float* __restrict__ out_idx, int n, int v)
{
    extern __shared__ float sm[];
    const int t   = threadIdx.x;
    const int w   = t >> 5;
    const int l   = t & 31;
    const int r0l = l >> 2;          // row within m16 block (0..7)
    const int cql = l & 3;           // quad column id
    const int m0  = blockIdx.x * MCTA;

    // ---- load X tile [128x128], split into tf32 hi/lo (RNA) ----
    #pragma unroll
    for (int i = 0; i < 16; i++) {
        int f   = i * 256 + t;           // float4 id
        int row = f >> 5;
        int c4  = (f & 31) * 4;
        float4 xv = *(const float4*)(x + (size_t)(m0 + row) * D128 + c4);
        float h0 = __uint_as_float(tf32_rna(xv.x));
        float h1 = __uint_as_float(tf32_rna(xv.y));
        float h2 = __uint_as_float(tf32_rna(xv.z));
        float h3 = __uint_as_float(tf32_rna(xv.w));
        float l0 = __uint_as_float(tf32_rna(xv.x - h0));
        float l1 = __uint_as_float(tf32_rna(xv.y - h1));
        float l2 = __uint_as_float(tf32_rna(xv.z - h2));
        float l3 = __uint_as_float(tf32_rna(xv.w - h3));
        int base = row * 132 + c4;
        *(float4*)(sm + XH + base) = make_float4(h0, h1, h2, h3);
        *(float4*)(sm + XL + base) = make_float4(l0, l1, l2, l3);
    }

    const float x2r0 = g_x2[m0 + w * 16 + r0l];
    const float x2r1 = g_x2[m0 + w * 16 + r0l + 8];

    float e[16][4];
    #pragma unroll
    for (int i = 0; i < 16; i++)
        #pragma unroll
        for (int j = 0; j < 4; j++) e[i][j] = 0.0f;

    float wsum0 = 0.0f, wsum1 = 0.0f;
    float mind0 = 3.4e38f, mind1 = 3.4e38f;
    int   mini0 = 0, mini1 = 0;

    const int arow0 = (w * 16 + r0l) * 132;
    const int arow1 = arow0 + 8 * 132;
    const int NTILES = v / VT;   // 128

    for (int tile = 0; tile < NTILES; tile++) {
        __syncthreads();   // previous tile's GEMM2 reads of CH/CL are done
        const int v0 = tile * VT;
        // ---- load C tile [64x128], split hi/lo ----
        #pragma unroll
        for (int i = 0; i < 8; i++) {
            int f   = i * 256 + t;
            int row = f >> 5;
            int c4  = (f & 31) * 4;
            float4 cv = *(const float4*)(cb + (size_t)(v0 + row) * D128 + c4);
            float h0 = __uint_as_float(tf32_rna(cv.x));
            float h1 = __uint_as_float(tf32_rna(cv.y));
            float h2 = __uint_as_float(tf32_rna(cv.z));
            float h3 = __uint_as_float(tf32_rna(cv.w));
            float l0 = __uint_as_float(tf32_rna(cv.x - h0));
            float l1 = __uint_as_float(tf32_rna(cv.y - h1));
            float l2 = __uint_as_float(tf32_rna(cv.z - h2));
            float l3 = __uint_as_float(tf32_rna(cv.w - h3));
            int base = row * 132 + c4;
            *(float4*)(sm + CHo + base) = make_float4(h0, h1, h2, h3);
            *(float4*)(sm + CLo + base) = make_float4(l0, l1, l2, l3);
        }
        if (t < VT) sm[C2S + t] = g_c2[v0 + t];
        __syncthreads();

        // ---- GEMM1: S[16 x 64] per warp, 4 tf32 products ----
        float s[8][4];
        #pragma unroll
        for (int i = 0; i < 8; i++)
            #pragma unroll
            for (int j = 0; j < 4; j++) s[i][j] = 0.0f;

        #pragma unroll 2
        for (int kt = 0; kt < 16; kt++) {
            const int k0 = kt * 8 + cql;
            uint32_t ah[4], al[4];
            ah[0] = fbits(sm[XH + arow0 + k0]);
            ah[1] = fbits(sm[XH + arow1 + k0]);
            ah[2] = fbits(sm[XH + arow0 + k0 + 4]);
            ah[3] = fbits(sm[XH + arow1 + k0 + 4]);
            al[0] = fbits(sm[XL + arow0 + k0]);
            al[1] = fbits(sm[XL + arow1 + k0]);
            al[2] = fbits(sm[XL + arow0 + k0 + 4]);
            al[3] = fbits(sm[XL + arow1 + k0 + 4]);
            #pragma unroll
            for (int nt = 0; nt < 8; nt++) {
                int br = (nt * 8 + r0l) * 132 + k0;
                uint32_t bh0 = fbits(sm[CHo + br]);
                uint32_t bh1 = fbits(sm[CHo + br + 4]);
                uint32_t bl0 = fbits(sm[CLo + br]);
                uint32_t bl1 = fbits(sm[CLo + br + 4]);
                mma8(s[nt], ah, bh0, bh1);
                mma8(s[nt], al, bh0, bh1);
                mma8(s[nt], ah, bl0, bl1);
                mma8(s[nt], al, bl0, bl1);
            }
        }

        // ---- epilogue: d = sqrt(max(x2+c2-2S,0)); track min/sum; W -> tf32 ----
        uint32_t wreg[8][4];
        #pragma unroll
        for (int nt = 0; nt < 8; nt++) {
            float c2a = sm[C2S + nt * 8 + 2 * cql];
            float c2b = sm[C2S + nt * 8 + 2 * cql + 1];
            int ib = v0 + nt * 8 + 2 * cql;

            float d00 = sqrtf(fmaxf(fmaf(-2.0f, s[nt][0], x2r0 + c2a), 0.0f));
            float d01 = sqrtf(fmaxf(fmaf(-2.0f, s[nt][1], x2r0 + c2b), 0.0f));
            float d10 = sqrtf(fmaxf(fmaf(-2.0f, s[nt][2], x2r1 + c2a), 0.0f));
            float d11 = sqrtf(fmaxf(fmaf(-2.0f, s[nt][3], x2r1 + c2b), 0.0f));

            if (d00 < mind0) { mind0 = d00; mini0 = ib; }
            if (d01 < mind0) { mind0 = d01; mini0 = ib + 1; }
            if (d10 < mind1) { mind1 = d10; mini1 = ib; }
            if (d11 < mind1) { mind1 = d11; mini1 = ib + 1; }

            float w00 = d00 + EPSF, w01 = d01 + EPSF;
            float w10 = d10 + EPSF, w11 = d11 + EPSF;
            wsum0 += w00 + w01;
            wsum1 += w10 + w11;
            wreg[nt][0] = tf32_rna(w00);
            wreg[nt][1] = tf32_rna(w01);
            wreg[nt][2] = tf32_rna(w10);
            wreg[nt][3] = tf32_rna(w11);
        }

        // ---- GEMM2: E[16 x 128] += W[16 x 64] * C[64 x 128] (single tf32) ----
        const int slA = r0l * 4 + (cql >> 1);
        const int slB = slA + 2;
        const bool odd = (cql & 1) != 0;
        #pragma unroll
        for (int kt2 = 0; kt2 < 8; kt2++) {
            uint32_t v00 = __shfl_sync(0xffffffffu, wreg[kt2][0], slA);
            uint32_t v01 = __shfl_sync(0xffffffffu, wreg[kt2][1], slA);
            uint32_t v20 = __shfl_sync(0xffffffffu, wreg[kt2][2], slA);
            uint32_t v21 = __shfl_sync(0xffffffffu, wreg[kt2][3], slA);
            uint32_t u00 = __shfl_sync(0xffffffffu, wreg[kt2][0], slB);
            uint32_t u01 = __shfl_sync(0xffffffffu, wreg[kt2][1], slB);
            uint32_t u20 = __shfl_sync(0xffffffffu, wreg[kt2][2], slB);
            uint32_t u21 = __shfl_sync(0xffffffffu, wreg[kt2][3], slB);
            uint32_t a[4];
            a[0] = odd ? v01 : v00;   // (row,    k)
            a[1] = odd ? v21 : v20;   // (row+8,  k)
            a[2] = odd ? u01 : u00;   // (row,    k+4)
            a[3] = odd ? u21 : u20;   // (row+8,  k+4)
            const int kr = (kt2 * 8 + cql) * 132 + r0l;
            #pragma unroll
            for (int nt2 = 0; nt2 < 16; nt2++) {
                uint32_t b0 = fbits(sm[CHo + kr + nt2 * 8]);
                uint32_t b1 = fbits(sm[CHo + kr + nt2 * 8 + 4 * 132]);
                mma8(e[nt2], a, b0, b1);
            }
        }
    }

    // ---- quad reduction (lanes sharing l>>2 hold the same rows) ----
    #pragma unroll
    for (int off = 1; off <= 2; off <<= 1) {
        wsum0 += __shfl_xor_sync(0xffffffffu, wsum0, off);
        wsum1 += __shfl_xor_sync(0xffffffffu, wsum1, off);
        float od0 = __shfl_xor_sync(0xffffffffu, mind0, off);
        int   oi0 = __shfl_xor_sync(0xffffffffu, mini0, off);
        float od1 = __shfl_xor_sync(0xffffffffu, mind1, off);
        int   oi1 = __shfl_xor_sync(0xffffffffu, mini1, off);
        if (od0 < mind0 || (od0 == mind0 && oi0 < mini0)) { mind0 = od0; mini0 = oi0; }
        if (od1 < mind1 || (od1 == mind1 && oi1 < mini1)) { mind1 = od1; mini1 = oi1; }
    }
    const float inv0 = 1.0f / wsum0;
    const float inv1 = 1.0f / wsum1;

    const int grow0 = m0 + w * 16 + r0l;
    const int grow1 = grow0 + 8;
    #pragma unroll
    for (int nt2 = 0; nt2 < 16; nt2++) {
        int col = nt2 * 8 + 2 * cql;
        float2 s0 = make_float2(e[nt2][0] * inv0, e[nt2][1] * inv0);
        float2 s1 = make_float2(e[nt2][2] * inv1, e[nt2][3] * inv1);
        *(float2*)(out_embed + (size_t)grow0 * D128 + col) = s0;
        *(float2*)(out_embed + (size_t)grow1 * D128 + col) = s1;
    }
    if (out_idx != nullptr && cql == 0) {
        out_idx[grow0] = (float)mini0;
        out_idx[grow1] = (float)mini1;
    }
}

extern "C" void kernel_launch(void* const* d_in, const int* in_sizes, int n_in,
                              void* d_out, int out_size) {
    const float* x  = (const float*)d_in[0];
    const float* cb = (const float*)d_in[1];
    int n = in_sizes[0] / D128;   // 16384
    int v = in_sizes[1] / D128;   // 8192
    float* out  = (float*)d_out;
    float* oidx = ((long long)out_size >= (long long)n * D128 + n)
                      ? out + (size_t)n * D128 : nullptr;

    int nblocks = ((n + v) * 32 + 255) / 256;
    norms_kernel<<<nblocks, 256>>>(x, cb, n, v);

    cudaFuncSetAttribute(softvq_mma, cudaFuncAttributeMaxDynamicSharedMemorySize,
                         SMEM_FLOATS * sizeof(float));
    softvq_mma<<<n / MCTA, 256, SMEM_FLOATS * sizeof(float)>>>(x, cb, out, oidx, n, v);
}

// round 5
// speedup vs baseline: 2.9769x; 1.0690x over previous
#include <cuda_runtime.h>
#include <cstdint>

#define D128 128
#define VT   64
#define MCTA 128
#define THR  512
#define EPSF 1e-8f

__device__ float g_x2[16384];
__device__ float g_c2[8192];

// smem float offsets
#define XF   0              // 128 x 132 fp32 X tile
#define CH   16896          // 64 x 132 tf32-hi C tile
#define CL   25344          // 64 x 132 tf32-lo C tile
#define WB   33792          // 64 x 136 k-major W buffer
#define C2S  42496          // 64 codeword norms
#define SMEM_FLOATS 42560   // 170,240 bytes
// end-of-kernel reuse: RS_* over CH/CL region, inv over WB region
#define RS_SUM  CH
#define RS_MIND (CH + 2048)
#define RS_MINI (CH + 4096)
#define RINV    WB

static __device__ __forceinline__ uint32_t tf32_rna(float x) {
    uint32_t r; asm("cvt.rna.tf32.f32 %0, %1;" : "=r"(r) : "f"(x)); return r;
}
static __device__ __forceinline__ uint32_t fbits(float x) { return __float_as_uint(x); }

static __device__ __forceinline__ void mma8(float* d, const uint32_t* a,
                                            uint32_t b0, uint32_t b1) {
    asm volatile("mma.sync.aligned.m16n8k8.row.col.f32.tf32.tf32.f32 "
        "{%0,%1,%2,%3}, {%4,%5,%6,%7}, {%8,%9}, {%0,%1,%2,%3};"
        : "+f"(d[0]), "+f"(d[1]), "+f"(d[2]), "+f"(d[3])
        : "r"(a[0]), "r"(a[1]), "r"(a[2]), "r"(a[3]), "r"(b0), "r"(b1));
}

// -------- norms pre-kernel (one warp per row) --------
__global__ void norms_kernel(const float* __restrict__ x,
                             const float* __restrict__ cb, int n, int v) {
    int gw   = (blockIdx.x * blockDim.x + threadIdx.x) >> 5;
    int lane = threadIdx.x & 31;
    if (gw >= n + v) return;
    const float* src = (gw < n) ? (x + (size_t)gw * D128) : (cb + (size_t)(gw - n) * D128);
    float4 val = ((const float4*)src)[lane];
    float s = val.x*val.x + val.y*val.y + val.z*val.z + val.w*val.w;
    #pragma unroll
    for (int off = 16; off; off >>= 1) s += __shfl_xor_sync(0xffffffffu, s, off);
    if (lane == 0) { if (gw < n) g_x2[gw] = s; else g_c2[gw - n] = s; }
}

// -------- fused SoftVQ, 16 warps: 32 rows/warp, V- and N- quarter splits --------
__global__ void __launch_bounds__(THR, 1) softvq_mma(
    const float* __restrict__ x, const float* __restrict__ cb,
    float* __restrict__ out_embed, float* __restrict__ out_idx, int n, int v)
{
    extern __shared__ float sm[];
    const int t   = threadIdx.x;
    const int w   = t >> 5;
    const int l   = t & 31;
    const int r0l = l >> 2;          // row within m16 block (0..7)
    const int cql = l & 3;           // quad column id
    const int g   = w >> 2;          // row-group (0..3): rows g*32 .. g*32+31
    const int q   = w & 3;           // quarter split id (0..3)
    const int m0  = blockIdx.x * MCTA;

    // ---- load X tile [128x128] fp32 into smem (stride 132) ----
    #pragma unroll
    for (int i = 0; i < 8; i++) {
        int f   = i * THR + t;
        int row = f >> 5;
        int c4  = (f & 31) * 4;
        float4 xv = *(const float4*)(x + (size_t)(m0 + row) * D128 + c4);
        *(float4*)(sm + XF + row * 132 + c4) = xv;
    }

    float x2r[2][2];
    #pragma unroll
    for (int mb = 0; mb < 2; mb++) {
        x2r[mb][0] = g_x2[m0 + g * 32 + mb * 16 + r0l];
        x2r[mb][1] = g_x2[m0 + g * 32 + mb * 16 + r0l + 8];
    }

    float e[2][4][4];
    #pragma unroll
    for (int mb = 0; mb < 2; mb++)
        #pragma unroll
        for (int i = 0; i < 4; i++)
            #pragma unroll
            for (int j = 0; j < 4; j++) e[mb][i][j] = 0.0f;

    float wsum[2][2] = {{0.f,0.f},{0.f,0.f}};
    float mind[2][2] = {{3.4e38f,3.4e38f},{3.4e38f,3.4e38f}};
    int   mini[2][2] = {{1<<30,1<<30},{1<<30,1<<30}};

    const int NTILES = v / VT;   // 128

    for (int tile = 0; tile < NTILES; tile++) {
        __syncthreads();   // prev tile's GEMM2 reads of CH/CL/WB complete
        const int v0 = tile * VT;
        // ---- load C tile [64x128], split hi/lo (RNA) ----
        #pragma unroll
        for (int i = 0; i < 4; i++) {
            int f   = i * THR + t;
            int row = f >> 5;
            int c4  = (f & 31) * 4;
            float4 cv = *(const float4*)(cb + (size_t)(v0 + row) * D128 + c4);
            float h0 = __uint_as_float(tf32_rna(cv.x));
            float h1 = __uint_as_float(tf32_rna(cv.y));
            float h2 = __uint_as_float(tf32_rna(cv.z));
            float h3 = __uint_as_float(tf32_rna(cv.w));
            float l0 = __uint_as_float(tf32_rna(cv.x - h0));
            float l1 = __uint_as_float(tf32_rna(cv.y - h1));
            float l2 = __uint_as_float(tf32_rna(cv.z - h2));
            float l3 = __uint_as_float(tf32_rna(cv.w - h3));
            int base = row * 132 + c4;
            *(float4*)(sm + CH + base) = make_float4(h0, h1, h2, h3);
            *(float4*)(sm + CL + base) = make_float4(l0, l1, l2, l3);
        }
        if (t < VT) sm[C2S + t] = g_c2[v0 + t];
        __syncthreads();

        // ---- GEMM1: S[32 x 16] per warp, 3 tf32 products, on-the-fly A split ----
        float s[2][2][4];
        #pragma unroll
        for (int mb = 0; mb < 2; mb++)
            #pragma unroll
            for (int i = 0; i < 2; i++)
                #pragma unroll
                for (int j = 0; j < 4; j++) s[mb][i][j] = 0.0f;

        #pragma unroll 2
        for (int kt = 0; kt < 16; kt++) {
            const int k0 = kt * 8 + cql;
            uint32_t ah[2][4], al[2][4];
            #pragma unroll
            for (int mb = 0; mb < 2; mb++) {
                int rb = (g * 32 + mb * 16 + r0l) * 132;
                float xv0 = sm[XF + rb + k0];
                float xv1 = sm[XF + rb + 8 * 132 + k0];
                float xv2 = sm[XF + rb + k0 + 4];
                float xv3 = sm[XF + rb + 8 * 132 + k0 + 4];
                ah[mb][0] = tf32_rna(xv0);
                ah[mb][1] = tf32_rna(xv1);
                ah[mb][2] = tf32_rna(xv2);
                ah[mb][3] = tf32_rna(xv3);
                al[mb][0] = tf32_rna(xv0 - __uint_as_float(ah[mb][0]));
                al[mb][1] = tf32_rna(xv1 - __uint_as_float(ah[mb][1]));
                al[mb][2] = tf32_rna(xv2 - __uint_as_float(ah[mb][2]));
                al[mb][3] = tf32_rna(xv3 - __uint_as_float(ah[mb][3]));
            }
            #pragma unroll
            for (int nt = 0; nt < 2; nt++) {
                int br = (q * 16 + nt * 8 + r0l) * 132 + k0;
                uint32_t bh0 = fbits(sm[CH + br]);
                uint32_t bh1 = fbits(sm[CH + br + 4]);
                uint32_t bl0 = fbits(sm[CL + br]);
                uint32_t bl1 = fbits(sm[CL + br + 4]);
                #pragma unroll
                for (int mb = 0; mb < 2; mb++) {
                    mma8(s[mb][nt], ah[mb], bh0, bh1);
                    mma8(s[mb][nt], al[mb], bh0, bh1);
                    mma8(s[mb][nt], ah[mb], bl0, bl1);
                }
            }
        }

        // ---- epilogue: d, min/sum, W -> tf32 into k-major smem buffer ----
        #pragma unroll
        for (int mb = 0; mb < 2; mb++) {
            #pragma unroll
            for (int nt = 0; nt < 2; nt++) {
                const float* sv = s[mb][nt];
                int cwb  = q * 16 + nt * 8 + 2 * cql;
                float c2a = sm[C2S + cwb];
                float c2b = sm[C2S + cwb + 1];
                int ib = v0 + cwb;

                float d00 = sqrtf(fmaxf(fmaf(-2.0f, sv[0], x2r[mb][0] + c2a), 0.0f));
                float d01 = sqrtf(fmaxf(fmaf(-2.0f, sv[1], x2r[mb][0] + c2b), 0.0f));
                float d10 = sqrtf(fmaxf(fmaf(-2.0f, sv[2], x2r[mb][1] + c2a), 0.0f));
                float d11 = sqrtf(fmaxf(fmaf(-2.0f, sv[3], x2r[mb][1] + c2b), 0.0f));

                if (d00 < mind[mb][0]) { mind[mb][0] = d00; mini[mb][0] = ib; }
                if (d01 < mind[mb][0]) { mind[mb][0] = d01; mini[mb][0] = ib + 1; }
                if (d10 < mind[mb][1]) { mind[mb][1] = d10; mini[mb][1] = ib; }
                if (d11 < mind[mb][1]) { mind[mb][1] = d11; mini[mb][1] = ib + 1; }

                float w00 = d00 + EPSF, w01 = d01 + EPSF;
                float w10 = d10 + EPSF, w11 = d11 + EPSF;
                wsum[mb][0] += w00 + w01;
                wsum[mb][1] += w10 + w11;

                int row = g * 32 + mb * 16 + r0l;
                sm[WB + cwb * 136 + row]           = __uint_as_float(tf32_rna(w00));
                sm[WB + (cwb + 1) * 136 + row]     = __uint_as_float(tf32_rna(w01));
                sm[WB + cwb * 136 + row + 8]       = __uint_as_float(tf32_rna(w10));
                sm[WB + (cwb + 1) * 136 + row + 8] = __uint_as_float(tf32_rna(w11));
            }
        }
        __syncthreads();   // WB complete for all warps

        // ---- GEMM2: E[32 x 32] += W[32 x 64] * C[64 x cols q*32..] ----
        #pragma unroll 2
        for (int kt2 = 0; kt2 < 8; kt2++) {
            const int kk = kt2 * 8 + cql;
            uint32_t a[2][4];
            #pragma unroll
            for (int mb = 0; mb < 2; mb++) {
                int row = g * 32 + mb * 16 + r0l;
                a[mb][0] = fbits(sm[WB + kk * 136 + row]);
                a[mb][1] = fbits(sm[WB + kk * 136 + row + 8]);
                a[mb][2] = fbits(sm[WB + (kk + 4) * 136 + row]);
                a[mb][3] = fbits(sm[WB + (kk + 4) * 136 + row + 8]);
            }
            #pragma unroll
            for (int nt2 = 0; nt2 < 4; nt2++) {
                int col = q * 32 + nt2 * 8 + r0l;
                uint32_t b0 = fbits(sm[CH + kk * 132 + col]);
                uint32_t b1 = fbits(sm[CH + (kk + 4) * 132 + col]);
                mma8(e[0][nt2], a[0], b0, b1);
                mma8(e[1][nt2], a[1], b0, b1);
            }
        }
    }

    // ---- final reduction: combine per-warp partials across the 4 q-splits ----
    __syncthreads();   // last GEMM2 reads of CH/WB done; safe to reuse
    #pragma unroll
    for (int mb = 0; mb < 2; mb++)
        #pragma unroll
        for (int r = 0; r < 2; r++) {
            int row = g * 32 + mb * 16 + r0l + r * 8;
            int bi  = row * 16 + q * 4 + cql;
            sm[RS_SUM  + bi] = wsum[mb][r];
            sm[RS_MIND + bi] = mind[mb][r];
            ((int*)sm)[RS_MINI + bi] = mini[mb][r];
        }
    __syncthreads();
    if (t < MCTA) {
        float ssum = 0.0f, bd = 3.4e38f;
        int bi = 1 << 30;
        #pragma unroll
        for (int j = 0; j < 16; j++) {
            ssum += sm[RS_SUM + t * 16 + j];
            float dj = sm[RS_MIND + t * 16 + j];
            int   ij = ((int*)sm)[RS_MINI + t * 16 + j];
            if (dj < bd || (dj == bd && ij < bi)) { bd = dj; bi = ij; }
        }
        sm[RINV + t] = 1.0f / ssum;
        if (out_idx != nullptr) out_idx[m0 + t] = (float)bi;
    }
    __syncthreads();

    // ---- embed output: each warp writes its 32 rows x 32 cols ----
    #pragma unroll
    for (int mb = 0; mb < 2; mb++) {
        int row0 = g * 32 + mb * 16 + r0l;
        float inv0 = sm[RINV + row0];
        float inv1 = sm[RINV + row0 + 8];
        #pragma unroll
        for (int nt2 = 0; nt2 < 4; nt2++) {
            int col = q * 32 + nt2 * 8 + 2 * cql;
            float2 o0 = make_float2(e[mb][nt2][0] * inv0, e[mb][nt2][1] * inv0);
            float2 o1 = make_float2(e[mb][nt2][2] * inv1, e[mb][nt2][3] * inv1);
            *(float2*)(out_embed + (size_t)(m0 + row0) * D128 + col)     = o0;
            *(float2*)(out_embed + (size_t)(m0 + row0 + 8) * D128 + col) = o1;
        }
    }
}

extern "C" void kernel_launch(void* const* d_in, const int* in_sizes, int n_in,
                              void* d_out, int out_size) {
    const float* x  = (const float*)d_in[0];
    const float* cb = (const float*)d_in[1];
    int n = in_sizes[0] / D128;   // 16384
    int v = in_sizes[1] / D128;   // 8192
    float* out  = (float*)d_out;
    float* oidx = ((long long)out_size >= (long long)n * D128 + n)
                      ? out + (size_t)n * D128 : nullptr;

    int nblocks = ((n + v) * 32 + 255) / 256;
    norms_kernel<<<nblocks, 256>>>(x, cb, n, v);

    cudaFuncSetAttribute(softvq_mma, cudaFuncAttributeMaxDynamicSharedMemorySize,
                         SMEM_FLOATS * sizeof(float));
    softvq_mma<<<n / MCTA, THR, SMEM_FLOATS * sizeof(float)>>>(x, cb, out, oidx, n, v);
}